// round 14
// baseline (speedup 1.0000x reference)
#include <cuda_runtime.h>
#include <cuda_bf16.h>

typedef unsigned int u32;

#define TPB 256
#define SCALE 0.17677669529663687f

// ---------------------------------------------------------------------------
// B=2, C=96, D=H=W=64, WS=8, N=64 tok/window, HEADS=3, HD=32.
// 3 branches x 8192 windows; CTA = 1 window (M=64), 256 threads, 8 warps,
// 2 CTAs/SM. mma.sync.m16n8k16 bf16, 3-pass split bf16.
// Pipelined head loop: warps 0-3 run register-resident attention(h) then
// q-GEMM(h+1); warps 4-7 run k/v-GEMM(h+1) concurrently (registers), and
// store k/v to smem only after a named barrier guarantees attention(h) has
// consumed the old k/v. Single-buffered KV, smem 76KB -> weights stay in L1D.
// ---------------------------------------------------------------------------

// Pre-packed weights: [br][mat: h0,h1,h2,proj][part hi/lo][nt12][ks6][lane32][2]u32
__device__ unsigned char g_wpk[3 * 4 * 2 * 18432];
// Expanded rpb bias in fragment order: [(br*3+h)*4+mt][lane32][32 floats]
__device__ float g_bias[3 * 3 * 4 * 1024];

__global__ void wprep(const float* __restrict__ qkv_w,
                      const float* __restrict__ proj_w,
                      const float* __restrict__ rpb_table,
                      const int* __restrict__ rpb_index) {
    int i = blockIdx.x * 256 + threadIdx.x;          // 147456 total
    if (i < 110592) {
        int k = i % 96, n = (i / 96) % 96, mat = (i / 9216) % 4, br = i / 36864;
        float wv;
        if (mat < 3) {
            int sub = n >> 5, dim = n & 31;          // 0=q,1=k,2=v
            wv = qkv_w[(br * 288 + sub * 96 + mat * 32 + dim) * 96 + k];
            if (sub == 0) wv *= SCALE;
        } else {
            wv = proj_w[(br * 96 + n) * 96 + k];
        }
        __nv_bfloat16 hi = __float2bfloat16(wv);
        __nv_bfloat16 lo = __float2bfloat16(wv - __bfloat162float(hi));
        int nt = n >> 3, ks = k >> 4;
        int lane = ((n & 7) << 2) | ((k >> 1) & 3);
        int rb = (k >> 3) & 1;
        size_t base = (size_t)(br * 4 + mat) * 36864;
        size_t off = (size_t)(nt * 6 + ks) * 256 + lane * 8 + rb * 4 + (k & 1) * 2;
        *(__nv_bfloat16*)(g_wpk + base + off)         = hi;
        *(__nv_bfloat16*)(g_wpk + base + 18432 + off) = lo;
    } else if (i < 147456) {
        int j = i - 110592;                          // 36864 bias entries
        int br = j / 12288;
        int h  = (j >> 12) % 3;
        int mt = (j >> 10) & 3;
        int l  = (j >> 5) & 31;
        int r  = j & 31;
        int n = mt * 16 + (l >> 2) + ((r >> 1) & 1) * 8;
        int m = (r >> 2) * 8 + (l & 3) * 2 + (r & 1);
        g_bias[j] = rpb_table[(br * 225 + rpb_index[n * 64 + m]) * 3 + h];
    }
}

__device__ __forceinline__ void mma16816(float* c, const uint4 a, const uint2 b) {
    asm volatile("mma.sync.aligned.m16n8k16.row.col.f32.bf16.bf16.f32 "
        "{%0,%1,%2,%3}, {%4,%5,%6,%7}, {%8,%9}, {%0,%1,%2,%3};"
        : "+f"(c[0]), "+f"(c[1]), "+f"(c[2]), "+f"(c[3])
        : "r"(a.x), "r"(a.y), "r"(a.z), "r"(a.w), "r"(b.x), "r"(b.y));
}

__device__ __forceinline__ void packsplit(float v0, float v1, u32& H, u32& L) {
    __nv_bfloat16 h0 = __float2bfloat16(v0);
    __nv_bfloat16 h1 = __float2bfloat16(v1);
    __nv_bfloat16 l0 = __float2bfloat16(v0 - __bfloat162float(h0));
    __nv_bfloat16 l1 = __float2bfloat16(v1 - __bfloat162float(h1));
    H = (u32)*(unsigned short*)&h0 | ((u32)*(unsigned short*)&h1 << 16);
    L = (u32)*(unsigned short*)&l0 | ((u32)*(unsigned short*)&l1 << 16);
}

__device__ __forceinline__ int x_off(int br, int b, int c, int s, int p, int q) {
    int d, h, w;
    if (br == 0)      { d = s; h = p; w = q; }   // image=(b,d), spatial (h,w)
    else if (br == 1) { d = q; h = p; w = s; }   // image=(b,w), spatial (h,d)
    else              { d = p; h = s; w = q; }   // image=(b,h), spatial (d,w)
    return (((b * 96 + c) * 64 + d) * 64 + h) * 64 + w;
}

// smem byte offsets (per-CTA total 76032 -> 2 CTAs/SM, 152KB -> 76KB L1D)
#define AXO  0        // x packed-A [2part][4mt][6ks][512B] : 24576 (lo +12288)
#define A2O  24576    // attn-out packed-A, same shape      : 24576 (lo +12288)
#define QO   49152    // q packed-A [2p][4mt][2ks][512]  : 8192 (lo +4096)
#define KO   57344    // k packed-B [2p][8nt][2ks][256]  : 8192 (lo +4096)
#define VO   65536    // v packed-B [2p][4nt][4ks][256] : 8192 (lo +4096)
#define BQO  73728    // [3][96] f32 qkv bias (q pre-scaled)
#define PBO  74880    // 96 f32
#define INVO 75264    // 96 f32
#define SHO  75648    // 96 f32
#define SMEM_BYTES 76032

// k/v fragment store (shared by head-0 GEMM1 and pipelined kv-GEMM)
__device__ __forceinline__ void store_kv(unsigned char* smc, int nt, int mt,
                                         int l, int r0, int j2,
                                         float v0, float v1) {
    if (nt < 8) {                     // k -> packed-B
        u32 H, L; packsplit(v0, v1, H, L);
        int ntk = nt - 4;
        int tok8 = mt * 2 + j2;
        int o = KO + (tok8 * 2 + (ntk >> 1)) * 256 + l * 8 + (ntk & 1) * 4;
        *(u32*)(smc + o)        = H;
        *(u32*)(smc + o + 4096) = L;
    } else {                          // v -> packed-B (transposed)
        int ntv = nt - 8;
        #pragma unroll
        for (int t2 = 0; t2 < 2; ++t2) {
            int d = ntv * 8 + (l & 3) * 2 + t2;
            float vv = t2 ? v1 : v0;
            __nv_bfloat16 hi = __float2bfloat16(vv);
            __nv_bfloat16 lo = __float2bfloat16(vv - __bfloat162float(hi));
            int o = VO + ((d >> 3) * 4 + mt) * 256
                    + (((d & 7) << 2) | ((r0 >> 1) & 3)) * 8
                    + j2 * 4 + (r0 & 1) * 2;
            *(__nv_bfloat16*)(smc + o)        = hi;
            *(__nv_bfloat16*)(smc + o + 4096) = lo;
        }
    }
}

template<bool ATOMIC>
__global__ __launch_bounds__(TPB, 2)
void swin_mma_kernel(
    const float* __restrict__ x,
    const float* __restrict__ qkv_b, const float* __restrict__ proj_b,
    const float* __restrict__ bn_g, const float* __restrict__ bn_b,
    const float* __restrict__ bn_m, const float* __restrict__ bn_v,
    float* __restrict__ out, int br)
{
    extern __shared__ unsigned char smc[];
    float* bqs  = (float*)(smc + BQO);
    float* pbs  = (float*)(smc + PBO);
    float* invs = (float*)(smc + INVO);
    float* shs  = (float*)(smc + SHO);

    const int tid = threadIdx.x;
    const int wrp = tid >> 5;
    const int l   = tid & 31;

    const int bid = blockIdx.x;
    const int g   = bid & 127;          // image index inner -> L2 sharing
    const int win = bid >> 7;           // 0..63
    const int wi  = win >> 3;
    const int wj  = win & 7;
    const int b   = g >> 6;
    const int s   = g & 63;

    if (tid < 96) {
        float inv = bn_g[br * 96 + tid] * rsqrtf(bn_v[br * 96 + tid] + 1e-5f);
        invs[tid] = inv;
        shs[tid]  = bn_b[br * 96 + tid] - bn_m[br * 96 + tid] * inv;
        pbs[tid]  = proj_b[br * 96 + tid];
    }
    for (int i = tid; i < 288; i += TPB) {
        int h = i / 96, u = i - h * 96;
        int sub = u >> 5, dim = u & 31;
        float v = qkv_b[br * 288 + sub * 96 + h * 32 + dim];
        if (sub == 0) v *= SCALE;
        bqs[i] = v;
    }

    // ---- load x -> packed-A (split bf16) ----------------------------------
    for (int i = tid; i < 6144; i += TPB) {
        int row = i & 63, c = i >> 6;                 // c 0..95
        int p = wi * 8 + (row >> 3), q = wj * 8 + (row & 7);
        float v = x[x_off(br, b, c, s, p, q)];
        __nv_bfloat16 hi = __float2bfloat16(v);
        __nv_bfloat16 lo = __float2bfloat16(v - __bfloat162float(hi));
        int mt = row >> 4, rr = row & 15, ks = c >> 4;
        int ln = ((rr & 7) << 2) | ((c >> 1) & 3);
        int rg = (rr >> 3) | (((c >> 3) & 1) << 1);
        int off = (mt * 6 + ks) * 512 + ln * 16 + rg * 4 + (c & 1) * 2;
        *(__nv_bfloat16*)(smc + AXO + off)         = hi;
        *(__nv_bfloat16*)(smc + AXO + 12288 + off) = lo;
    }
    __syncthreads();

    // ---- head-0 GEMM1: all 8 warps (q,k,v for h=0) ------------------------
    {
        const int mt = wrp & 3, ng = wrp >> 2;
        const unsigned char* wp = g_wpk + (size_t)(br * 4 + 0) * 36864;
        float acc[6][4];
        #pragma unroll
        for (int j = 0; j < 6; ++j) {
            int c0 = (ng * 6 + j) * 8 + (l & 3) * 2;
            acc[j][0] = bqs[c0]; acc[j][1] = bqs[c0 + 1];
            acc[j][2] = acc[j][0]; acc[j][3] = acc[j][1];
        }
        #pragma unroll
        for (int ks = 0; ks < 6; ++ks) {
            uint4 ah = *(const uint4*)(smc + AXO + (mt * 6 + ks) * 512 + l * 16);
            uint4 al = *(const uint4*)(smc + AXO + 12288 + (mt * 6 + ks) * 512 + l * 16);
            #pragma unroll
            for (int j = 0; j < 6; ++j) {
                int nt = ng * 6 + j;
                uint2 bh = __ldg((const uint2*)(wp + (nt * 6 + ks) * 256 + l * 8));
                uint2 bl = __ldg((const uint2*)(wp + 18432 + (nt * 6 + ks) * 256 + l * 8));
                mma16816(acc[j], ah, bh);
                mma16816(acc[j], ah, bl);
                mma16816(acc[j], al, bh);
            }
        }
        const int r0 = l >> 2;
        #pragma unroll
        for (int j = 0; j < 6; ++j) {
            int nt = ng * 6 + j;
            #pragma unroll
            for (int j2 = 0; j2 < 2; ++j2) {
                float v0 = acc[j][2 * j2], v1 = acc[j][2 * j2 + 1];
                if (nt < 4) {                         // q -> packed-A
                    u32 H, L; packsplit(v0, v1, H, L);
                    int o = QO + (mt * 2 + (nt >> 1)) * 512
                            + l * 16 + (j2 | ((nt & 1) << 1)) * 4;
                    *(u32*)(smc + o)        = H;
                    *(u32*)(smc + o + 4096) = L;
                } else {
                    store_kv(smc, nt, mt, l, r0, j2, v0, v1);
                }
            }
        }
    }

    // ======================= pipelined head loop ===========================
    for (int h = 0; h < 3; ++h) {
        __syncthreads();   // KV(h)/QO(h) visible to attention warps

        if (wrp < 4) {
            // =============== attention(h), fully in registers ===============
            const int mt = wrp;

            // q A-frags
            uint4 qh[2], ql[2];
            #pragma unroll
            for (int ks = 0; ks < 2; ++ks) {
                qh[ks] = *(const uint4*)(smc + QO + (mt * 2 + ks) * 512 + l * 16);
                ql[ks] = *(const uint4*)(smc + QO + 4096 + (mt * 2 + ks) * 512 + l * 16);
            }

            // QK^T
            float acc[8][4];
            #pragma unroll
            for (int j = 0; j < 8; ++j)
                acc[j][0] = acc[j][1] = acc[j][2] = acc[j][3] = 0.f;
            #pragma unroll
            for (int ks = 0; ks < 2; ++ks) {
                #pragma unroll
                for (int j = 0; j < 8; ++j) {
                    uint2 bh = *(const uint2*)(smc + KO + (j * 2 + ks) * 256 + l * 8);
                    uint2 bl = *(const uint2*)(smc + KO + 4096 + (j * 2 + ks) * 256 + l * 8);
                    mma16816(acc[j], qh[ks], bh);
                    mma16816(acc[j], qh[ks], bl);
                    mma16816(acc[j], ql[ks], bh);
                }
            }

            // bias: fragment-ordered, after the mma loop
            const float4* gb4 = (const float4*)(g_bias
                                + (((br * 3 + h) * 4 + mt) << 10) + l * 32);
            #pragma unroll
            for (int j = 0; j < 8; ++j) {
                float4 bv = __ldg(gb4 + j);
                acc[j][0] += bv.x; acc[j][1] += bv.y;
                acc[j][2] += bv.z; acc[j][3] += bv.w;
            }

            // softmax: rows r0 (c0,c1) and r0+8 (c2,c3), quad-shuffle reduce
            float mx0 = -1e30f, mx1 = -1e30f;
            #pragma unroll
            for (int j = 0; j < 8; ++j) {
                mx0 = fmaxf(mx0, fmaxf(acc[j][0], acc[j][1]));
                mx1 = fmaxf(mx1, fmaxf(acc[j][2], acc[j][3]));
            }
            mx0 = fmaxf(mx0, __shfl_xor_sync(0xffffffff, mx0, 1));
            mx0 = fmaxf(mx0, __shfl_xor_sync(0xffffffff, mx0, 2));
            mx1 = fmaxf(mx1, __shfl_xor_sync(0xffffffff, mx1, 1));
            mx1 = fmaxf(mx1, __shfl_xor_sync(0xffffffff, mx1, 2));
            float s0 = 0.f, s1 = 0.f;
            #pragma unroll
            for (int j = 0; j < 8; ++j) {
                acc[j][0] = __expf(acc[j][0] - mx0); s0 += acc[j][0];
                acc[j][1] = __expf(acc[j][1] - mx0); s0 += acc[j][1];
                acc[j][2] = __expf(acc[j][2] - mx1); s1 += acc[j][2];
                acc[j][3] = __expf(acc[j][3] - mx1); s1 += acc[j][3];
            }
            s0 += __shfl_xor_sync(0xffffffff, s0, 1);
            s0 += __shfl_xor_sync(0xffffffff, s0, 2);
            s1 += __shfl_xor_sync(0xffffffff, s1, 1);
            s1 += __shfl_xor_sync(0xffffffff, s1, 2);
            float rs0 = 1.f / s0, rs1 = 1.f / s1;
            #pragma unroll
            for (int j = 0; j < 8; ++j) {
                acc[j][0] *= rs0; acc[j][1] *= rs0;
                acc[j][2] *= rs1; acc[j][3] *= rs1;
            }

            // pack P -> A-frags in registers
            uint4 ph[4], pl[4];
            #pragma unroll
            for (int ks = 0; ks < 4; ++ks) {
                packsplit(acc[2 * ks][0],     acc[2 * ks][1],     ph[ks].x, pl[ks].x);
                packsplit(acc[2 * ks][2],     acc[2 * ks][3],     ph[ks].y, pl[ks].y);
                packsplit(acc[2 * ks + 1][0], acc[2 * ks + 1][1], ph[ks].z, pl[ks].z);
                packsplit(acc[2 * ks + 1][2], acc[2 * ks + 1][3], ph[ks].w, pl[ks].w);
            }

            // AV
            float av[4][4];
            #pragma unroll
            for (int nt = 0; nt < 4; ++nt)
                av[nt][0] = av[nt][1] = av[nt][2] = av[nt][3] = 0.f;
            #pragma unroll
            for (int ks = 0; ks < 4; ++ks) {
                #pragma unroll
                for (int nt = 0; nt < 4; ++nt) {
                    uint2 vh = *(const uint2*)(smc + VO + (nt * 4 + ks) * 256 + l * 8);
                    uint2 vl = *(const uint2*)(smc + VO + 4096 + (nt * 4 + ks) * 256 + l * 8);
                    mma16816(av[nt], ph[ks], vh);
                    mma16816(av[nt], ph[ks], vl);
                    mma16816(av[nt], pl[ks], vh);
                }
            }

            // KV(h) fully consumed -> let producers overwrite
            asm volatile("bar.sync 1, 256;" ::: "memory");

            // attn-out -> A2 packed-A (split bf16)
            #pragma unroll
            for (int nt = 0; nt < 4; ++nt) {
                int ksa  = 2 * h + (nt >> 1);
                int rghi = (nt & 1) << 1;
                #pragma unroll
                for (int j2 = 0; j2 < 2; ++j2) {
                    u32 H, L;
                    packsplit(av[nt][2 * j2], av[nt][2 * j2 + 1], H, L);
                    int o = A2O + (mt * 6 + ksa) * 512 + l * 16 + (j2 | rghi) * 4;
                    *(u32*)(smc + o)         = H;
                    *(u32*)(smc + o + 12288) = L;
                }
            }

            // q-GEMM(h+1): 4 nt, writes this warp's own QO region
            if (h < 2) {
                const unsigned char* wp = g_wpk + (size_t)(br * 4 + h + 1) * 36864;
                float qa[4][4];
                #pragma unroll
                for (int nt = 0; nt < 4; ++nt) {
                    int c0 = nt * 8 + (l & 3) * 2;
                    qa[nt][0] = bqs[(h + 1) * 96 + c0];
                    qa[nt][1] = bqs[(h + 1) * 96 + c0 + 1];
                    qa[nt][2] = qa[nt][0]; qa[nt][3] = qa[nt][1];
                }
                #pragma unroll
                for (int ks = 0; ks < 6; ++ks) {
                    uint4 ah = *(const uint4*)(smc + AXO + (mt * 6 + ks) * 512 + l * 16);
                    uint4 al = *(const uint4*)(smc + AXO + 12288 + (mt * 6 + ks) * 512 + l * 16);
                    #pragma unroll
                    for (int nt = 0; nt < 4; ++nt) {
                        uint2 bh = __ldg((const uint2*)(wp + (nt * 6 + ks) * 256 + l * 8));
                        uint2 bl = __ldg((const uint2*)(wp + 18432 + (nt * 6 + ks) * 256 + l * 8));
                        mma16816(qa[nt], ah, bh);
                        mma16816(qa[nt], ah, bl);
                        mma16816(qa[nt], al, bh);
                    }
                }
                #pragma unroll
                for (int nt = 0; nt < 4; ++nt) {
                    #pragma unroll
                    for (int j2 = 0; j2 < 2; ++j2) {
                        u32 H, L;
                        packsplit(qa[nt][2 * j2], qa[nt][2 * j2 + 1], H, L);
                        int o = QO + (mt * 2 + (nt >> 1)) * 512
                                + l * 16 + (j2 | ((nt & 1) << 1)) * 4;
                        *(u32*)(smc + o)        = H;
                        *(u32*)(smc + o + 4096) = L;
                    }
                }
            }
        } else {
            // =============== k/v-GEMM(h+1) on warps 4-7 =====================
            const int mt = wrp - 4;
            float acc[8][4];
            if (h < 2) {
                const unsigned char* wp = g_wpk + (size_t)(br * 4 + h + 1) * 36864;
                #pragma unroll
                for (int j = 0; j < 8; ++j) {
                    int c0 = (4 + j) * 8 + (l & 3) * 2;
                    acc[j][0] = bqs[(h + 1) * 96 + c0];
                    acc[j][1] = bqs[(h + 1) * 96 + c0 + 1];
                    acc[j][2] = acc[j][0]; acc[j][3] = acc[j][1];
                }
                #pragma unroll
                for (int ks = 0; ks < 6; ++ks) {
                    uint4 ah = *(const uint4*)(smc + AXO + (mt * 6 + ks) * 512 + l * 16);
                    uint4 al = *(const uint4*)(smc + AXO + 12288 + (mt * 6 + ks) * 512 + l * 16);
                    #pragma unroll
                    for (int j = 0; j < 8; ++j) {
                        int nt = 4 + j;
                        uint2 bh = __ldg((const uint2*)(wp + (nt * 6 + ks) * 256 + l * 8));
                        uint2 bl = __ldg((const uint2*)(wp + 18432 + (nt * 6 + ks) * 256 + l * 8));
                        mma16816(acc[j], ah, bh);
                        mma16816(acc[j], ah, bl);
                        mma16816(acc[j], al, bh);
                    }
                }
            }

            // wait until attention(h) has consumed old KV
            asm volatile("bar.sync 1, 256;" ::: "memory");

            if (h < 2) {
                const int r0 = l >> 2;
                #pragma unroll
                for (int j = 0; j < 8; ++j) {
                    #pragma unroll
                    for (int j2 = 0; j2 < 2; ++j2)
                        store_kv(smc, 4 + j, mt, l, r0, j2,
                                 acc[j][2 * j2], acc[j][2 * j2 + 1]);
                }
            }
        }
    }
    __syncthreads();

    // ======================= proj + BN + LeakyReLU =========================
    {
        const int mt = wrp & 3, ng = wrp >> 2;
        const unsigned char* wp = g_wpk + (size_t)(br * 4 + 3) * 36864;
        float acc[6][4];
        #pragma unroll
        for (int j = 0; j < 6; ++j) {
            int c0 = (ng * 6 + j) * 8 + (l & 3) * 2;
            acc[j][0] = pbs[c0]; acc[j][1] = pbs[c0 + 1];
            acc[j][2] = pbs[c0]; acc[j][3] = pbs[c0 + 1];
        }
        #pragma unroll
        for (int ks = 0; ks < 6; ++ks) {
            uint4 ah = *(const uint4*)(smc + A2O + (mt * 6 + ks) * 512 + l * 16);
            uint4 al = *(const uint4*)(smc + A2O + 12288 + (mt * 6 + ks) * 512 + l * 16);
            #pragma unroll
            for (int j = 0; j < 6; ++j) {
                int nt = ng * 6 + j;
                uint2 bh = __ldg((const uint2*)(wp + (nt * 6 + ks) * 256 + l * 8));
                uint2 bl = __ldg((const uint2*)(wp + 18432 + (nt * 6 + ks) * 256 + l * 8));
                mma16816(acc[j], ah, bh);
                mma16816(acc[j], ah, bl);
                mma16816(acc[j], al, bh);
            }
        }
        const int r0 = l >> 2;
        #pragma unroll
        for (int j = 0; j < 6; ++j) {
            int c0 = (ng * 6 + j) * 8 + (l & 3) * 2;
            #pragma unroll
            for (int j2 = 0; j2 < 2; ++j2) {
                int tl = mt * 16 + r0 + 8 * j2;
                int p = wi * 8 + (tl >> 3);
                int q = wj * 8 + (tl & 7);
                #pragma unroll
                for (int t2 = 0; t2 < 2; ++t2) {
                    int co = c0 + t2;
                    float v = acc[j][2 * j2 + t2];
                    float yn = v * invs[co] + shs[co];
                    yn = (yn >= 0.f) ? yn : 0.01f * yn;
                    int off = x_off(br, b, co, s, p, q);
                    if (ATOMIC) atomicAdd(&out[off], yn);
                    else        out[off] = yn;
                }
            }
        }
    }
}

extern "C" void kernel_launch(void* const* d_in, const int* in_sizes, int n_in,
                              void* d_out, int out_size)
{
    (void)in_sizes; (void)n_in; (void)out_size;
    const float* x         = (const float*)d_in[0];
    const float* qkv_w     = (const float*)d_in[1];
    const float* qkv_b     = (const float*)d_in[2];
    const float* proj_w    = (const float*)d_in[3];
    const float* proj_b    = (const float*)d_in[4];
    const float* rpb_table = (const float*)d_in[5];
    const float* bn_g      = (const float*)d_in[6];
    const float* bn_b      = (const float*)d_in[7];
    const float* bn_m      = (const float*)d_in[8];
    const float* bn_v      = (const float*)d_in[9];
    const int*   rpb_index = (const int*)d_in[10];
    float* out = (float*)d_out;

    wprep<<<576, 256>>>(qkv_w, proj_w, rpb_table, rpb_index);

    cudaFuncSetAttribute(swin_mma_kernel<false>,
                         cudaFuncAttributeMaxDynamicSharedMemorySize, SMEM_BYTES);
    cudaFuncSetAttribute(swin_mma_kernel<true>,
                         cudaFuncAttributeMaxDynamicSharedMemorySize, SMEM_BYTES);

    // Branch 0: plain stores (full output coverage kills 0xAA poison)
    swin_mma_kernel<false><<<8192, TPB, SMEM_BYTES>>>(
        x, qkv_b, proj_b, bn_g, bn_b, bn_m, bn_v, out, 0);
    // Branches 1 & 2: accumulate
    swin_mma_kernel<true><<<8192, TPB, SMEM_BYTES>>>(
        x, qkv_b, proj_b, bn_g, bn_b, bn_m, bn_v, out, 1);
    swin_mma_kernel<true><<<8192, TPB, SMEM_BYTES>>>(
        x, qkv_b, proj_b, bn_g, bn_b, bn_m, bn_v, out, 2);
}

// round 15
// speedup vs baseline: 1.1317x; 1.1317x over previous
#include <cuda_runtime.h>
#include <cuda_bf16.h>

typedef unsigned int u32;

#define TPB 256
#define SCALE 0.17677669529663687f

// ---------------------------------------------------------------------------
// B=2, C=96, D=H=W=64, WS=8, N=64 tok/window, HEADS=3, HD=32.
// 3 branches x 8192 windows; CTA = 1 window (M=64), 256 threads, 8 warps,
// 2 CTAs/SM. mma.sync.m16n8k16 bf16, 3-pass split bf16.
// No smem weight staging (B-frags via __ldg; 76KB smem -> weights L1-resident).
// Attention register-resident on warps 0-3.
// Bias layout FIXED to [ja][lane][4]: consecutive lanes read consecutive
// float4 -> 4 wavefronts per LDG.128 instead of 32.
// ---------------------------------------------------------------------------

// Pre-packed weights: [br][mat: h0,h1,h2,proj][part hi/lo][nt12][ks6][lane32][2]u32
__device__ unsigned char g_wpk[3 * 4 * 2 * 18432];
// Expanded rpb bias: [(br*3+h)*4+mt][ja(8)][lane(32)][4 floats]  (coalesced)
__device__ float g_bias[3 * 3 * 4 * 1024];

__global__ void wprep(const float* __restrict__ qkv_w,
                      const float* __restrict__ proj_w,
                      const float* __restrict__ rpb_table,
                      const int* __restrict__ rpb_index) {
    int i = blockIdx.x * 256 + threadIdx.x;          // 147456 total
    if (i < 110592) {
        int k = i % 96, n = (i / 96) % 96, mat = (i / 9216) % 4, br = i / 36864;
        float wv;
        if (mat < 3) {
            int sub = n >> 5, dim = n & 31;          // 0=q,1=k,2=v
            wv = qkv_w[(br * 288 + sub * 96 + mat * 32 + dim) * 96 + k];
            if (sub == 0) wv *= SCALE;
        } else {
            wv = proj_w[(br * 96 + n) * 96 + k];
        }
        __nv_bfloat16 hi = __float2bfloat16(wv);
        __nv_bfloat16 lo = __float2bfloat16(wv - __bfloat162float(hi));
        int nt = n >> 3, ks = k >> 4;
        int lane = ((n & 7) << 2) | ((k >> 1) & 3);
        int rb = (k >> 3) & 1;
        size_t base = (size_t)(br * 4 + mat) * 36864;
        size_t off = (size_t)(nt * 6 + ks) * 256 + lane * 8 + rb * 4 + (k & 1) * 2;
        *(__nv_bfloat16*)(g_wpk + base + off)         = hi;
        *(__nv_bfloat16*)(g_wpk + base + 18432 + off) = lo;
    } else if (i < 147456) {
        int j2 = i - 110592;                         // 36864 bias entries
        int br    = j2 / 12288;
        int rem   = j2 % 12288;
        int h     = rem >> 12;                       // 0..2
        int mt    = (rem >> 10) & 3;
        int inner = rem & 1023;
        int ja = inner >> 7;                         // acc index 0..7
        int l  = (inner >> 2) & 31;                  // lane
        int ca = inner & 3;                          // within-acc 0..3
        int n = mt * 16 + (l >> 2) + ((ca >> 1) & 1) * 8;
        int m = ja * 8 + (l & 3) * 2 + (ca & 1);
        g_bias[j2] = rpb_table[(br * 225 + rpb_index[n * 64 + m]) * 3 + h];
    }
}

__device__ __forceinline__ void mma16816(float* c, const uint4 a, const uint2 b) {
    asm volatile("mma.sync.aligned.m16n8k16.row.col.f32.bf16.bf16.f32 "
        "{%0,%1,%2,%3}, {%4,%5,%6,%7}, {%8,%9}, {%0,%1,%2,%3};"
        : "+f"(c[0]), "+f"(c[1]), "+f"(c[2]), "+f"(c[3])
        : "r"(a.x), "r"(a.y), "r"(a.z), "r"(a.w), "r"(b.x), "r"(b.y));
}

__device__ __forceinline__ void packsplit(float v0, float v1, u32& H, u32& L) {
    __nv_bfloat16 h0 = __float2bfloat16(v0);
    __nv_bfloat16 h1 = __float2bfloat16(v1);
    __nv_bfloat16 l0 = __float2bfloat16(v0 - __bfloat162float(h0));
    __nv_bfloat16 l1 = __float2bfloat16(v1 - __bfloat162float(h1));
    H = (u32)*(unsigned short*)&h0 | ((u32)*(unsigned short*)&h1 << 16);
    L = (u32)*(unsigned short*)&l0 | ((u32)*(unsigned short*)&l1 << 16);
}

__device__ __forceinline__ int x_off(int br, int b, int c, int s, int p, int q) {
    int d, h, w;
    if (br == 0)      { d = s; h = p; w = q; }   // image=(b,d), spatial (h,w)
    else if (br == 1) { d = q; h = p; w = s; }   // image=(b,w), spatial (h,d)
    else              { d = p; h = s; w = q; }   // image=(b,h), spatial (d,w)
    return (((b * 96 + c) * 64 + d) * 64 + h) * 64 + w;
}

// smem byte offsets (per-CTA total 76032 -> 2 CTAs/SM, 152KB -> 76KB L1D)
#define AXO  0        // x packed-A [2part][4mt][6ks][512B] : 24576 (lo +12288)
#define A2O  24576    // attn-out packed-A, same shape      : 24576 (lo +12288)
#define QO   49152    // q packed-A [2p][4mt][2ks][512]  : 8192 (lo +4096)
#define KO   57344    // k packed-B [2p][8nt][2ks][256]  : 8192 (lo +4096)
#define VO   65536    // v packed-B [2p][4nt][4ks][256] : 8192 (lo +4096)
#define BQO  73728    // [3][96] f32 qkv bias (q pre-scaled)
#define PBO  74880    // 96 f32
#define INVO 75264    // 96 f32
#define SHO  75648    // 96 f32
#define SMEM_BYTES 76032

template<bool ATOMIC>
__global__ __launch_bounds__(TPB, 2)
void swin_mma_kernel(
    const float* __restrict__ x,
    const float* __restrict__ qkv_b, const float* __restrict__ proj_b,
    const float* __restrict__ bn_g, const float* __restrict__ bn_b,
    const float* __restrict__ bn_m, const float* __restrict__ bn_v,
    float* __restrict__ out, int br)
{
    extern __shared__ unsigned char smc[];
    float* bqs  = (float*)(smc + BQO);
    float* pbs  = (float*)(smc + PBO);
    float* invs = (float*)(smc + INVO);
    float* shs  = (float*)(smc + SHO);

    const int tid = threadIdx.x;
    const int wrp = tid >> 5;
    const int l   = tid & 31;

    const int bid = blockIdx.x;
    const int g   = bid & 127;          // image index inner -> L2 sharing
    const int win = bid >> 7;           // 0..63
    const int wi  = win >> 3;
    const int wj  = win & 7;
    const int b   = g >> 6;
    const int s   = g & 63;

    if (tid < 96) {
        float inv = bn_g[br * 96 + tid] * rsqrtf(bn_v[br * 96 + tid] + 1e-5f);
        invs[tid] = inv;
        shs[tid]  = bn_b[br * 96 + tid] - bn_m[br * 96 + tid] * inv;
        pbs[tid]  = proj_b[br * 96 + tid];
    }
    for (int i = tid; i < 288; i += TPB) {
        int h = i / 96, u = i - h * 96;
        int sub = u >> 5, dim = u & 31;
        float v = qkv_b[br * 288 + sub * 96 + h * 32 + dim];
        if (sub == 0) v *= SCALE;
        bqs[i] = v;
    }

    // ---- load x -> packed-A (split bf16) ----------------------------------
    for (int i = tid; i < 6144; i += TPB) {
        int row = i & 63, c = i >> 6;                 // c 0..95
        int p = wi * 8 + (row >> 3), q = wj * 8 + (row & 7);
        float v = x[x_off(br, b, c, s, p, q)];
        __nv_bfloat16 hi = __float2bfloat16(v);
        __nv_bfloat16 lo = __float2bfloat16(v - __bfloat162float(hi));
        int mt = row >> 4, rr = row & 15, ks = c >> 4;
        int ln = ((rr & 7) << 2) | ((c >> 1) & 3);
        int rg = (rr >> 3) | (((c >> 3) & 1) << 1);
        int off = (mt * 6 + ks) * 512 + ln * 16 + rg * 4 + (c & 1) * 2;
        *(__nv_bfloat16*)(smc + AXO + off)         = hi;
        *(__nv_bfloat16*)(smc + AXO + 12288 + off) = lo;
    }
    __syncthreads();

    // ======================= per head ======================================
    for (int h = 0; h < 3; ++h) {
        // ---- GEMM1: [64 tok] x [96 outs] x K=96; B-frags direct from gmem --
        {
            const int mt = wrp & 3, ng = wrp >> 2;
            const unsigned char* wp = g_wpk + (size_t)(br * 4 + h) * 36864;
            float acc[6][4];
            #pragma unroll
            for (int j = 0; j < 6; ++j) {
                int c0 = (ng * 6 + j) * 8 + (l & 3) * 2;
                acc[j][0] = bqs[h * 96 + c0]; acc[j][1] = bqs[h * 96 + c0 + 1];
                acc[j][2] = acc[j][0];        acc[j][3] = acc[j][1];
            }
            #pragma unroll
            for (int ks = 0; ks < 6; ++ks) {
                uint4 ah = *(const uint4*)(smc + AXO + (mt * 6 + ks) * 512 + l * 16);
                uint4 al = *(const uint4*)(smc + AXO + 12288 + (mt * 6 + ks) * 512 + l * 16);
                #pragma unroll
                for (int j = 0; j < 6; ++j) {
                    int nt = ng * 6 + j;
                    uint2 bh = __ldg((const uint2*)(wp + (nt * 6 + ks) * 256 + l * 8));
                    uint2 bl = __ldg((const uint2*)(wp + 18432 + (nt * 6 + ks) * 256 + l * 8));
                    mma16816(acc[j], ah, bh);
                    mma16816(acc[j], ah, bl);
                    mma16816(acc[j], al, bh);
                }
            }
            const int r0 = l >> 2;
            #pragma unroll
            for (int j = 0; j < 6; ++j) {
                int nt = ng * 6 + j;
                #pragma unroll
                for (int j2 = 0; j2 < 2; ++j2) {
                    float v0 = acc[j][2 * j2], v1 = acc[j][2 * j2 + 1];
                    if (nt < 4) {                         // q -> packed-A
                        u32 H, L; packsplit(v0, v1, H, L);
                        int o = QO + (mt * 2 + (nt >> 1)) * 512
                                + l * 16 + (j2 | ((nt & 1) << 1)) * 4;
                        *(u32*)(smc + o)        = H;
                        *(u32*)(smc + o + 4096) = L;
                    } else if (nt < 8) {                  // k -> packed-B
                        u32 H, L; packsplit(v0, v1, H, L);
                        int ntk = nt - 4;
                        int tok8 = mt * 2 + j2;
                        int o = KO + (tok8 * 2 + (ntk >> 1)) * 256
                                + l * 8 + (ntk & 1) * 4;
                        *(u32*)(smc + o)        = H;
                        *(u32*)(smc + o + 4096) = L;
                    } else {                              // v -> packed-B (transposed)
                        int ntv = nt - 8;
                        #pragma unroll
                        for (int t2 = 0; t2 < 2; ++t2) {
                            int d = ntv * 8 + (l & 3) * 2 + t2;
                            float vv = t2 ? v1 : v0;
                            __nv_bfloat16 hi = __float2bfloat16(vv);
                            __nv_bfloat16 lo = __float2bfloat16(vv - __bfloat162float(hi));
                            int o = VO + ((d >> 3) * 4 + mt) * 256
                                    + (((d & 7) << 2) | ((r0 >> 1) & 3)) * 8
                                    + j2 * 4 + (r0 & 1) * 2;
                            *(__nv_bfloat16*)(smc + o)        = hi;
                            *(__nv_bfloat16*)(smc + o + 4096) = lo;
                        }
                    }
                }
            }
        }
        __syncthreads();

        if (wrp < 4) {
            // =============== attention, fully in registers ==================
            const int mt = wrp;

            // q A-frags
            uint4 qh[2], ql[2];
            #pragma unroll
            for (int ks = 0; ks < 2; ++ks) {
                qh[ks] = *(const uint4*)(smc + QO + (mt * 2 + ks) * 512 + l * 16);
                ql[ks] = *(const uint4*)(smc + QO + 4096 + (mt * 2 + ks) * 512 + l * 16);
            }

            // QK^T
            float acc[8][4];
            #pragma unroll
            for (int j = 0; j < 8; ++j)
                acc[j][0] = acc[j][1] = acc[j][2] = acc[j][3] = 0.f;
            #pragma unroll
            for (int ks = 0; ks < 2; ++ks) {
                #pragma unroll
                for (int j = 0; j < 8; ++j) {
                    uint2 bh = *(const uint2*)(smc + KO + (j * 2 + ks) * 256 + l * 8);
                    uint2 bl = *(const uint2*)(smc + KO + 4096 + (j * 2 + ks) * 256 + l * 8);
                    mma16816(acc[j], qh[ks], bh);
                    mma16816(acc[j], qh[ks], bl);
                    mma16816(acc[j], ql[ks], bh);
                }
            }

            // bias: [ja][lane][4] layout -> consecutive lanes, coalesced
            const float4* gb4 = (const float4*)g_bias
                                + ((br * 3 + h) * 4 + mt) * 256 + l;
            #pragma unroll
            for (int j = 0; j < 8; ++j) {
                float4 bv = __ldg(gb4 + j * 32);
                acc[j][0] += bv.x; acc[j][1] += bv.y;
                acc[j][2] += bv.z; acc[j][3] += bv.w;
            }

            // softmax: rows r0 (c0,c1) and r0+8 (c2,c3), quad-shuffle reduce
            float mx0 = -1e30f, mx1 = -1e30f;
            #pragma unroll
            for (int j = 0; j < 8; ++j) {
                mx0 = fmaxf(mx0, fmaxf(acc[j][0], acc[j][1]));
                mx1 = fmaxf(mx1, fmaxf(acc[j][2], acc[j][3]));
            }
            mx0 = fmaxf(mx0, __shfl_xor_sync(0xffffffff, mx0, 1));
            mx0 = fmaxf(mx0, __shfl_xor_sync(0xffffffff, mx0, 2));
            mx1 = fmaxf(mx1, __shfl_xor_sync(0xffffffff, mx1, 1));
            mx1 = fmaxf(mx1, __shfl_xor_sync(0xffffffff, mx1, 2));
            float s0 = 0.f, s1 = 0.f;
            #pragma unroll
            for (int j = 0; j < 8; ++j) {
                acc[j][0] = __expf(acc[j][0] - mx0); s0 += acc[j][0];
                acc[j][1] = __expf(acc[j][1] - mx0); s0 += acc[j][1];
                acc[j][2] = __expf(acc[j][2] - mx1); s1 += acc[j][2];
                acc[j][3] = __expf(acc[j][3] - mx1); s1 += acc[j][3];
            }
            s0 += __shfl_xor_sync(0xffffffff, s0, 1);
            s0 += __shfl_xor_sync(0xffffffff, s0, 2);
            s1 += __shfl_xor_sync(0xffffffff, s1, 1);
            s1 += __shfl_xor_sync(0xffffffff, s1, 2);
            float rs0 = 1.f / s0, rs1 = 1.f / s1;
            #pragma unroll
            for (int j = 0; j < 8; ++j) {
                acc[j][0] *= rs0; acc[j][1] *= rs0;
                acc[j][2] *= rs1; acc[j][3] *= rs1;
            }

            // pack P -> A-frags in registers (acc layout == A-frag layout)
            uint4 ph[4], pl[4];
            #pragma unroll
            for (int ks = 0; ks < 4; ++ks) {
                packsplit(acc[2 * ks][0],     acc[2 * ks][1],     ph[ks].x, pl[ks].x);
                packsplit(acc[2 * ks][2],     acc[2 * ks][3],     ph[ks].y, pl[ks].y);
                packsplit(acc[2 * ks + 1][0], acc[2 * ks + 1][1], ph[ks].z, pl[ks].z);
                packsplit(acc[2 * ks + 1][2], acc[2 * ks + 1][3], ph[ks].w, pl[ks].w);
            }

            // AV
            float av[4][4];
            #pragma unroll
            for (int nt = 0; nt < 4; ++nt)
                av[nt][0] = av[nt][1] = av[nt][2] = av[nt][3] = 0.f;
            #pragma unroll
            for (int ks = 0; ks < 4; ++ks) {
                #pragma unroll
                for (int nt = 0; nt < 4; ++nt) {
                    uint2 vh = *(const uint2*)(smc + VO + (nt * 4 + ks) * 256 + l * 8);
                    uint2 vl = *(const uint2*)(smc + VO + 4096 + (nt * 4 + ks) * 256 + l * 8);
                    mma16816(av[nt], ph[ks], vh);
                    mma16816(av[nt], ph[ks], vl);
                    mma16816(av[nt], pl[ks], vh);
                }
            }

            // attn-out -> A2 packed-A (split bf16)
            #pragma unroll
            for (int nt = 0; nt < 4; ++nt) {
                int ksa  = 2 * h + (nt >> 1);
                int rghi = (nt & 1) << 1;
                #pragma unroll
                for (int j2 = 0; j2 < 2; ++j2) {
                    u32 H, L;
                    packsplit(av[nt][2 * j2], av[nt][2 * j2 + 1], H, L);
                    int o = A2O + (mt * 6 + ksa) * 512 + l * 16 + (j2 | rghi) * 4;
                    *(u32*)(smc + o)         = H;
                    *(u32*)(smc + o + 12288) = L;
                }
            }
        }
        __syncthreads();
    }

    // ======================= proj + BN + LeakyReLU =========================
    {
        const int mt = wrp & 3, ng = wrp >> 2;
        const unsigned char* wp = g_wpk + (size_t)(br * 4 + 3) * 36864;
        float acc[6][4];
        #pragma unroll
        for (int j = 0; j < 6; ++j) {
            int c0 = (ng * 6 + j) * 8 + (l & 3) * 2;
            acc[j][0] = pbs[c0]; acc[j][1] = pbs[c0 + 1];
            acc[j][2] = pbs[c0]; acc[j][3] = pbs[c0 + 1];
        }
        #pragma unroll
        for (int ks = 0; ks < 6; ++ks) {
            uint4 ah = *(const uint4*)(smc + A2O + (mt * 6 + ks) * 512 + l * 16);
            uint4 al = *(const uint4*)(smc + A2O + 12288 + (mt * 6 + ks) * 512 + l * 16);
            #pragma unroll
            for (int j = 0; j < 6; ++j) {
                int nt = ng * 6 + j;
                uint2 bh = __ldg((const uint2*)(wp + (nt * 6 + ks) * 256 + l * 8));
                uint2 bl = __ldg((const uint2*)(wp + 18432 + (nt * 6 + ks) * 256 + l * 8));
                mma16816(acc[j], ah, bh);
                mma16816(acc[j], ah, bl);
                mma16816(acc[j], al, bh);
            }
        }
        const int r0 = l >> 2;
        #pragma unroll
        for (int j = 0; j < 6; ++j) {
            int c0 = (ng * 6 + j) * 8 + (l & 3) * 2;
            #pragma unroll
            for (int j2 = 0; j2 < 2; ++j2) {
                int tl = mt * 16 + r0 + 8 * j2;
                int p = wi * 8 + (tl >> 3);
                int q = wj * 8 + (tl & 7);
                #pragma unroll
                for (int t2 = 0; t2 < 2; ++t2) {
                    int co = c0 + t2;
                    float v = acc[j][2 * j2 + t2];
                    float yn = v * invs[co] + shs[co];
                    yn = (yn >= 0.f) ? yn : 0.01f * yn;
                    int off = x_off(br, b, co, s, p, q);
                    if (ATOMIC) atomicAdd(&out[off], yn);
                    else        out[off] = yn;
                }
            }
        }
    }
}

extern "C" void kernel_launch(void* const* d_in, const int* in_sizes, int n_in,
                              void* d_out, int out_size)
{
    (void)in_sizes; (void)n_in; (void)out_size;
    const float* x         = (const float*)d_in[0];
    const float* qkv_w     = (const float*)d_in[1];
    const float* qkv_b     = (const float*)d_in[2];
    const float* proj_w    = (const float*)d_in[3];
    const float* proj_b    = (const float*)d_in[4];
    const float* rpb_table = (const float*)d_in[5];
    const float* bn_g      = (const float*)d_in[6];
    const float* bn_b      = (const float*)d_in[7];
    const float* bn_m      = (const float*)d_in[8];
    const float* bn_v      = (const float*)d_in[9];
    const int*   rpb_index = (const int*)d_in[10];
    float* out = (float*)d_out;

    wprep<<<576, 256>>>(qkv_w, proj_w, rpb_table, rpb_index);

    cudaFuncSetAttribute(swin_mma_kernel<false>,
                         cudaFuncAttributeMaxDynamicSharedMemorySize, SMEM_BYTES);
    cudaFuncSetAttribute(swin_mma_kernel<true>,
                         cudaFuncAttributeMaxDynamicSharedMemorySize, SMEM_BYTES);

    // Branch 0: plain stores (full output coverage kills 0xAA poison)
    swin_mma_kernel<false><<<8192, TPB, SMEM_BYTES>>>(
        x, qkv_b, proj_b, bn_g, bn_b, bn_m, bn_v, out, 0);
    // Branches 1 & 2: accumulate
    swin_mma_kernel<true><<<8192, TPB, SMEM_BYTES>>>(
        x, qkv_b, proj_b, bn_g, bn_b, bn_m, bn_v, out, 1);
    swin_mma_kernel<true><<<8192, TPB, SMEM_BYTES>>>(
        x, qkv_b, proj_b, bn_g, bn_b, bn_m, bn_v, out, 2);
}